// round 13
// baseline (speedup 1.0000x reference)
#include <cuda_runtime.h>
#include <cstdint>

typedef unsigned long long u64;

#define BB   256
#define TT   2048
#define HH   256
#define PP   24
#define BC   2              // batch rows per CTA
#define NCTA (BB/BC)        // 128
#define NTHR 256            // 8 warps; each thread: 4 rows x 64 cols
#define NSMC 16             // W float4-chunks in smem per thread (slot 3)

// packed f32x2 ops
__device__ __forceinline__ void fma2(u64 &d, u64 a, u64 b) {
    asm("fma.rn.f32x2 %0, %1, %2, %0;" : "+l"(d) : "l"(a), "l"(b));
}
__device__ __forceinline__ void mul2(u64 &d, u64 a, u64 b) {
    asm("mul.rn.f32x2 %0, %1, %2;" : "=l"(d) : "l"(a), "l"(b));
}
__device__ __forceinline__ float2 unpk(u64 v) {
    float2 r; asm("mov.b64 {%0, %1}, %2;" : "=f"(r.x), "=f"(r.y) : "l"(v)); return r;
}

// SMEM layout:
//  [0, 64K)     sW[c][t] : W slot-3 chunk c of thread t (ulonglong2), c < NSMC
//  [64K, 68K)   h double buffer [2][BC][HH] floats (phi-swizzled, see below)
//  [68K, 84K)   x stage: interleaved (x_b0[ts], x_b1[ts]) u64 pairs, TT entries
#define SW_BYTES   ((size_t)NSMC * NTHR * 16)
#define HB_BYTES   ((size_t)2 * BC * HH * 4)
#define X_BYTES    ((size_t)TT * 8)
#define SMEM_TOTAL (SW_BYTES + HB_BYTES + X_BYTES)

// h float4-chunk i (= col>>2, 6 bits: i = 16k + c) stored at float4 position
//   phi(i) = ((i & 15) << 2) | ((i >> 4) ^ (i & 3))
// Reads (fixed c, lanes k=0..3): 4 float4 in one 64B block, distinct quads -> 1 wf.
// Writes (warp: rows t): 2-way bank conflict -> 2 wf per STS (accepted).
__device__ __forceinline__ int hphi(int i) {
    return (((i & 15) << 2) | ((i >> 4) ^ (i & 3)));
}
// word index within one 512-float h buffer for (col, b)
__device__ __forceinline__ int hword(int col, int b) {
    return b * HH + hphi(col >> 2) * 4 + (col & 3);
}

// fast tanh: 1 - 2/(e^{2x}+1). branch-free, inf-safe.
__device__ __forceinline__ float ftanh(float x) {
    float e = __expf(x + x);
    return 1.0f - __fdividef(2.0f, e + 1.0f);
}

__global__ void __launch_bounds__(NTHR, 1)
rnn_persistent_kernel(const float* __restrict__ x,
                      const float* __restrict__ W_ih,
                      const float* __restrict__ W_hh,
                      const float* __restrict__ b_ih,
                      const float* __restrict__ b_hh,
                      const float* __restrict__ W_out,
                      const float* __restrict__ b_out,
                      float* __restrict__ out)
{
    extern __shared__ char smem[];
    ulonglong2* sW   = (ulonglong2*)smem;
    float*      hbuf = (float*)(smem + SW_BYTES);
    u64*        sx2  = (u64*)(smem + SW_BYTES + HB_BYTES);

    const int t  = threadIdx.x;
    const int g  = t >> 2;      // row group: rows 4g..4g+3
    const int k  = t & 3;       // column strip: cols 64k..64k+63 (chunks 16k+c)
    const int b0 = blockIdx.x * BC;

    // ---- Prologue.
    // Slot-swizzle: physical slot jp holds logical row 4g + (jp ^ k)  (2-bit XOR)
    // -> select-free 2-level shfl tree; lane k ends owning row 4g+k = t.
    // Slots 0,1,2 -> registers (48 float4 = 192 regs). Slot 3 -> smem.
    const ulonglong2* Wv = (const ulonglong2*)W_hh;   // row stride = 64 float4
    ulonglong2 wr[48];
#pragma unroll
    for (int jp = 0; jp < 3; jp++)
#pragma unroll
        for (int c = 0; c < 16; c++)
            wr[jp*16 + c] = Wv[(size_t)(4*g + (jp ^ k)) * 64 + 16*k + c];
#pragma unroll
    for (int c = 0; c < 16; c++)
        sW[c * NTHR + t] = Wv[(size_t)(4*g + (3 ^ k)) * 64 + 16*k + c];

    // lane-owned output after reduction: row t, both batches
    const float bias = b_ih[t] + b_hh[t];
    const float wih  = W_ih[t];
    const int wpos0  = hword(t, 0);
    const int wpos1  = hword(t, 1);

    // precomputed strip-XOR offsets for h chunk addressing: kx[c&3] = k ^ (c&3)
    const int kx0 = k, kx1 = k ^ 1, kx2 = k ^ 2, kx3 = k ^ 3;

    // stage x as interleaved (b0, b1) pairs
    {
        const float* xg0 = x + (size_t)b0 * TT;
        const float* xg1 = x + (size_t)(b0 + 1) * TT;
#pragma unroll
        for (int q = t; q < TT; q += NTHR) {
            float2 p; p.x = xg0[q]; p.y = xg1[q];
            u64 v; asm("mov.b64 %0, {%1, %2};" : "=l"(v) : "f"(p.x), "f"(p.y));
            sx2[q] = v;
        }
    }
    hbuf[t] = 0.0f; hbuf[NTHR + t] = 0.0f;   // zero h buffer 0
    __syncthreads();

    int rb = 0;
    for (int ts = 0; ts < TT; ts++) {
        const ulonglong2* hv = (const ulonglong2*)(hbuf + rb * (BC * HH));
        // h chunk (b, c) at ulonglong2 index b*64 + 4c + (k ^ (c&3))

        // hoisted input projection (h-independent)
        float2 xf = unpk(sx2[ts]);
        const float pre0b = fmaf(xf.x, wih, bias);
        const float pre1b = fmaf(xf.y, wih, bias);

        u64 A[8];   // A[jp*2 + b] : partial for logical row 4g + (jp^k)
#pragma unroll
        for (int c = 0; c < 16; c++) {
            const int kxor = (c & 3) == 0 ? kx0 : ((c & 3) == 1 ? kx1 : ((c & 3) == 2 ? kx2 : kx3));
            ulonglong2 h0 = hv[4*c + kxor];
            ulonglong2 h1 = hv[64 + 4*c + kxor];
            ulonglong2 w3 = sW[c * NTHR + t];
            if (c == 0) {
#pragma unroll
                for (int jp = 0; jp < 3; jp++) {
                    ulonglong2 w = wr[jp*16];
                    mul2(A[jp*2],   h0.x, w.x); fma2(A[jp*2],   h0.y, w.y);
                    mul2(A[jp*2+1], h1.x, w.x); fma2(A[jp*2+1], h1.y, w.y);
                }
                mul2(A[6], h0.x, w3.x); fma2(A[6], h0.y, w3.y);
                mul2(A[7], h1.x, w3.x); fma2(A[7], h1.y, w3.y);
            } else {
#pragma unroll
                for (int jp = 0; jp < 3; jp++) {
                    ulonglong2 w = wr[jp*16 + c];
                    fma2(A[jp*2],   h0.x, w.x); fma2(A[jp*2],   h0.y, w.y);
                    fma2(A[jp*2+1], h1.x, w.x); fma2(A[jp*2+1], h1.y, w.y);
                }
                fma2(A[6], h0.x, w3.x); fma2(A[6], h0.y, w3.y);
                fma2(A[7], h1.x, w3.x); fma2(A[7], h1.y, w3.y);
            }
        }

        float s[8];
#pragma unroll
        for (int m = 0; m < 8; m++) { float2 f = unpk(A[m]); s[m] = f.x + f.y; }

        // Select-free 2-level tree (slot-swizzled accumulators).
        float r[4];
#pragma unroll
        for (int q = 0; q < 4; q++)            // q = qslot*2 + b, qslot<2
            r[q] = s[q] + __shfl_xor_sync(0xffffffffu, s[q + 4], 2);
        float v0 = r[0] + __shfl_xor_sync(0xffffffffu, r[2], 1);
        float v1 = r[1] + __shfl_xor_sync(0xffffffffu, r[3], 1);

        const int wo = (rb ^ 1) * (BC * HH);
        hbuf[wo + wpos0] = ftanh(v0 + pre0b);
        hbuf[wo + wpos1] = ftanh(v1 + pre1b);
        __syncthreads();
        rb ^= 1;
    }

    // ---- Epilogue: out[b,p] = h_T[b,:] . W_out[p,:] + b_out[p]  (h in buf 0)
    if (t < BC * PP) {
        const int bb = t / PP;
        const int p  = t % PP;
        const float* wo = W_out + (size_t)p * HH;
        float acc = b_out[p];
#pragma unroll 8
        for (int col = 0; col < HH; col++)
            acc = fmaf(hbuf[hword(col, bb)], wo[col], acc);
        out[(size_t)(b0 + bb) * PP + p] = acc;
    }
}

extern "C" void kernel_launch(void* const* d_in, const int* in_sizes, int n_in,
                              void* d_out, int out_size)
{
    const float* x     = (const float*)d_in[0];
    const float* W_ih  = (const float*)d_in[1];
    const float* W_hh  = (const float*)d_in[2];
    const float* b_ih  = (const float*)d_in[3];
    const float* b_hh  = (const float*)d_in[4];
    const float* W_out = (const float*)d_in[5];
    const float* b_out = (const float*)d_in[6];
    float* out = (float*)d_out;

    cudaFuncSetAttribute(rnn_persistent_kernel,
                         cudaFuncAttributeMaxDynamicSharedMemorySize, (int)SMEM_TOTAL);
    rnn_persistent_kernel<<<NCTA, NTHR, SMEM_TOTAL>>>(x, W_ih, W_hh, b_ih, b_hh,
                                                      W_out, b_out, out);
}

// round 14
// speedup vs baseline: 1.1346x; 1.1346x over previous
#include <cuda_runtime.h>
#include <cstdint>

typedef unsigned long long u64;

#define BB   256
#define TT   2048
#define HH   256
#define PP   24
#define BC   2              // batch rows per CTA
#define NCTA (BB/BC)        // 128
#define NTHR 256            // 8 warps; each thread: 8 rows x 32 cols
#define NSMC 22             // W float4-chunks in smem per thread

// packed f32x2 ops
__device__ __forceinline__ void fma2(u64 &d, u64 a, u64 b) {
    asm("fma.rn.f32x2 %0, %1, %2, %0;" : "+l"(d) : "l"(a), "l"(b));
}
__device__ __forceinline__ void mul2(u64 &d, u64 a, u64 b) {
    asm("mul.rn.f32x2 %0, %1, %2;" : "=l"(d) : "l"(a), "l"(b));
}
__device__ __forceinline__ float2 unpk(u64 v) {
    float2 r; asm("mov.b64 {%0, %1}, %2;" : "=f"(r.x), "=f"(r.y) : "l"(v)); return r;
}

// SMEM layout:
//  [0, 88K)     sW[c][t] : W smem chunk c of thread t (ulonglong2), c < NSMC
//               c in [0,6)  -> slot 5, chunks 2..7
//               c in [6,14) -> slot 6, chunks 0..7
//               c in [14,22)-> slot 7, chunks 0..7
//  [+0, +4K)    h double buffer [2][BC][HH] floats (XOR-swizzled, see hword)
//  [+0, +16K)   x stage: interleaved (x_b0[ts], x_b1[ts]) u64 pairs, TT entries
#define SW_BYTES   ((size_t)NSMC * NTHR * 16)
#define HB_BYTES   ((size_t)2 * BC * HH * 4)
#define X_BYTES    ((size_t)TT * 8)
#define SMEM_TOTAL (SW_BYTES + HB_BYTES + X_BYTES)

// storage word (within one 512-float h buffer) for (col, batch):
//   c=(col>>2)&7, kk=col>>5, j=col&3 ; float4 idx = c*8 + (kk^c)
// Reads (fixed c, lanes k=0..7): 8 distinct float4 in an 8-aligned block -> 1 wavefront.
// Writes (warp: rows 8g+k): 32 distinct banks -> 1 wavefront.
__device__ __forceinline__ int hword(int col, int b) {
    int c = (col >> 2) & 7, kk = col >> 5, j = col & 3;
    return b * HH + ((((c << 3) | (kk ^ c)) << 2) | j);
}

// fast tanh: 1 - 2/(e^{2x}+1). branch-free, inf-safe.
__device__ __forceinline__ float ftanh(float x) {
    float e = __expf(x + x);
    return 1.0f - __fdividef(2.0f, e + 1.0f);
}

__global__ void __launch_bounds__(NTHR, 1)
rnn_persistent_kernel(const float* __restrict__ x,
                      const float* __restrict__ W_ih,
                      const float* __restrict__ W_hh,
                      const float* __restrict__ b_ih,
                      const float* __restrict__ b_hh,
                      const float* __restrict__ W_out,
                      const float* __restrict__ b_out,
                      float* __restrict__ out)
{
    extern __shared__ char smem[];
    ulonglong2* sW   = (ulonglong2*)smem;
    float*      hbuf = (float*)(smem + SW_BYTES);
    u64*        sx2  = (u64*)(smem + SW_BYTES + HB_BYTES);

    const int t  = threadIdx.x;
    const int g  = t >> 3;      // row group: rows 8g..8g+7
    const int k  = t & 7;       // column strip: cols 32k..32k+31
    const int b0 = blockIdx.x * BC;

    // ---- Prologue.
    // Slot-swizzle: physical slot jp holds logical row (jp ^ k) -> select-free tree;
    // lane k still ends owning row 8g+k.
    // Slots 0..4 fully in RF; slot 5 chunks 0,1 in RF (42 float4 = 168 regs);
    // slot 5 chunks 2..7 + slots 6,7 in smem (22 chunks).
    const ulonglong2* Wv = (const ulonglong2*)W_hh;   // row stride = 64 float4
    ulonglong2 wr[42];
#pragma unroll
    for (int jp = 0; jp < 5; jp++)
#pragma unroll
        for (int c = 0; c < 8; c++)
            wr[jp*8 + c] = Wv[(size_t)(8*g + (jp ^ k)) * 64 + k*8 + c];
    wr[40] = Wv[(size_t)(8*g + (5 ^ k)) * 64 + k*8 + 0];
    wr[41] = Wv[(size_t)(8*g + (5 ^ k)) * 64 + k*8 + 1];
#pragma unroll
    for (int c = 2; c < 8; c++)   // slot 5, chunks 2..7 -> sW rows 0..5
        sW[(c - 2) * NTHR + t] = Wv[(size_t)(8*g + (5 ^ k)) * 64 + k*8 + c];
#pragma unroll
    for (int c = 0; c < 8; c++)   // slot 6 -> sW rows 6..13
        sW[(6 + c) * NTHR + t] = Wv[(size_t)(8*g + (6 ^ k)) * 64 + k*8 + c];
#pragma unroll
    for (int c = 0; c < 8; c++)   // slot 7 -> sW rows 14..21
        sW[(14 + c) * NTHR + t] = Wv[(size_t)(8*g + (7 ^ k)) * 64 + k*8 + c];

    // lane-owned outputs after reduction: row 8g+k, both batches
    const int myrow  = 8*g + k;
    const float bias = b_ih[myrow] + b_hh[myrow];
    const float wih  = W_ih[myrow];
    const int wpos0  = hword(myrow, 0);
    const int wpos1  = hword(myrow, 1);

    // stage x as interleaved (b0, b1) pairs
    {
        const float* xg0 = x + (size_t)b0 * TT;
        const float* xg1 = x + (size_t)(b0 + 1) * TT;
#pragma unroll
        for (int q = t; q < TT; q += NTHR) {
            float2 p; p.x = xg0[q]; p.y = xg1[q];
            u64 v; asm("mov.b64 %0, {%1, %2};" : "=l"(v) : "f"(p.x), "f"(p.y));
            sx2[q] = v;
        }
    }
    hbuf[t] = 0.0f; hbuf[NTHR + t] = 0.0f;   // zero h buffer 0
    __syncthreads();

    int rb = 0;
    for (int ts = 0; ts < TT; ts++) {
        const ulonglong2* hr = (const ulonglong2*)(hbuf + rb * (BC * HH));

        // hoisted input projection (h-independent): one LDS.64 + unpack
        float2 xf = unpk(sx2[ts]);
        const float pre0b = fmaf(xf.x, wih, bias);
        const float pre1b = fmaf(xf.y, wih, bias);

        u64 A[16];   // A[jp*2 + b] : partial for logical row (jp^k)
#pragma unroll
        for (int c = 0; c < 8; c++) {
            const int m0 = k ^ c;
            ulonglong2 h0 = hr[c*8 + m0];
            ulonglong2 h1 = hr[64 + c*8 + m0];
            ulonglong2 w5 = (c < 2) ? wr[40 + c] : sW[(c - 2) * NTHR + t];
            ulonglong2 w6 = sW[(6 + c) * NTHR + t];
            ulonglong2 w7 = sW[(14 + c) * NTHR + t];
            if (c == 0) {
#pragma unroll
                for (int jp = 0; jp < 5; jp++) {
                    ulonglong2 w = wr[jp*8];
                    mul2(A[jp*2],   h0.x, w.x); fma2(A[jp*2],   h0.y, w.y);
                    mul2(A[jp*2+1], h1.x, w.x); fma2(A[jp*2+1], h1.y, w.y);
                }
                mul2(A[10], h0.x, w5.x); fma2(A[10], h0.y, w5.y);
                mul2(A[11], h1.x, w5.x); fma2(A[11], h1.y, w5.y);
                mul2(A[12], h0.x, w6.x); fma2(A[12], h0.y, w6.y);
                mul2(A[13], h1.x, w6.x); fma2(A[13], h1.y, w6.y);
                mul2(A[14], h0.x, w7.x); fma2(A[14], h0.y, w7.y);
                mul2(A[15], h1.x, w7.x); fma2(A[15], h1.y, w7.y);
            } else {
#pragma unroll
                for (int jp = 0; jp < 5; jp++) {
                    ulonglong2 w = wr[jp*8 + c];
                    fma2(A[jp*2],   h0.x, w.x); fma2(A[jp*2],   h0.y, w.y);
                    fma2(A[jp*2+1], h1.x, w.x); fma2(A[jp*2+1], h1.y, w.y);
                }
                fma2(A[10], h0.x, w5.x); fma2(A[10], h0.y, w5.y);
                fma2(A[11], h1.x, w5.x); fma2(A[11], h1.y, w5.y);
                fma2(A[12], h0.x, w6.x); fma2(A[12], h0.y, w6.y);
                fma2(A[13], h1.x, w6.x); fma2(A[13], h1.y, w6.y);
                fma2(A[14], h0.x, w7.x); fma2(A[14], h0.y, w7.y);
                fma2(A[15], h1.x, w7.x); fma2(A[15], h1.y, w7.y);
            }
        }

        float s[16];
#pragma unroll
        for (int m = 0; m < 16; m++) { float2 f = unpk(A[m]); s[m] = f.x + f.y; }

        // Select-free tree (slot-swizzled accumulators).
        float r8[8];
#pragma unroll
        for (int q = 0; q < 8; q++)
            r8[q] = s[q] + __shfl_xor_sync(0xffffffffu, s[q + 8], 4);
        float r4[4];
#pragma unroll
        for (int q = 0; q < 4; q++)
            r4[q] = r8[q] + __shfl_xor_sync(0xffffffffu, r8[q + 4], 2);
        float v0 = r4[0] + __shfl_xor_sync(0xffffffffu, r4[2], 1);
        float v1 = r4[1] + __shfl_xor_sync(0xffffffffu, r4[3], 1);

        const int wo = (rb ^ 1) * (BC * HH);
        hbuf[wo + wpos0] = ftanh(v0 + pre0b);
        hbuf[wo + wpos1] = ftanh(v1 + pre1b);
        __syncthreads();
        rb ^= 1;
    }

    // ---- Epilogue: out[b,p] = h_T[b,:] . W_out[p,:] + b_out[p]  (h in buf 0)
    if (t < BC * PP) {
        const int bb = t / PP;
        const int p  = t % PP;
        const float* wo = W_out + (size_t)p * HH;
        float acc = b_out[p];
#pragma unroll 8
        for (int col = 0; col < HH; col++)
            acc = fmaf(hbuf[hword(col, bb)], wo[col], acc);
        out[(size_t)(b0 + bb) * PP + p] = acc;
    }
}

extern "C" void kernel_launch(void* const* d_in, const int* in_sizes, int n_in,
                              void* d_out, int out_size)
{
    const float* x     = (const float*)d_in[0];
    const float* W_ih  = (const float*)d_in[1];
    const float* W_hh  = (const float*)d_in[2];
    const float* b_ih  = (const float*)d_in[3];
    const float* b_hh  = (const float*)d_in[4];
    const float* W_out = (const float*)d_in[5];
    const float* b_out = (const float*)d_in[6];
    float* out = (float*)d_out;

    cudaFuncSetAttribute(rnn_persistent_kernel,
                         cudaFuncAttributeMaxDynamicSharedMemorySize, (int)SMEM_TOTAL);
    rnn_persistent_kernel<<<NCTA, NTHR, SMEM_TOTAL>>>(x, W_ih, W_hh, b_ih, b_hh,
                                                      W_out, b_out, out);
}

// round 15
// speedup vs baseline: 1.1371x; 1.0022x over previous
#include <cuda_runtime.h>
#include <cstdint>

typedef unsigned long long u64;

#define BB   256
#define TT   2048
#define HH   256
#define PP   24
#define BC   2              // batch rows per CTA
#define NCTA (BB/BC)        // 128
#define NTHR 256            // 8 warps; each thread: 8 rows x 32 cols
#define NSMC 24             // W float4-chunks in smem per thread (slots 5,6,7)

// packed f32x2 ops
__device__ __forceinline__ void fma2(u64 &d, u64 a, u64 b) {
    asm("fma.rn.f32x2 %0, %1, %2, %0;" : "+l"(d) : "l"(a), "l"(b));
}
__device__ __forceinline__ void mul2(u64 &d, u64 a, u64 b) {
    asm("mul.rn.f32x2 %0, %1, %2;" : "=l"(d) : "l"(a), "l"(b));
}
__device__ __forceinline__ float2 unpk(u64 v) {
    float2 r; asm("mov.b64 {%0, %1}, %2;" : "=f"(r.x), "=f"(r.y) : "l"(v)); return r;
}

// SMEM layout:
//  [0, 96K)     sW[c][t] : W chunk c of thread t (ulonglong2), c < NSMC
//  [96K,100K)   h double buffer [2][BC][HH] floats (XOR-swizzled, see hword)
//  [100K,116K)  x stage: interleaved (x_b0[ts], x_b1[ts]) u64 pairs, TT entries
#define SW_BYTES   ((size_t)NSMC * NTHR * 16)
#define HB_BYTES   ((size_t)2 * BC * HH * 4)
#define X_BYTES    ((size_t)TT * 8)
#define SMEM_TOTAL (SW_BYTES + HB_BYTES + X_BYTES)

// storage word (within one 512-float h buffer) for (col, batch):
//   c=(col>>2)&7, kk=col>>5, j=col&3 ; float4 idx = c*8 + (kk^c)
// Reads (fixed c, lanes k=0..7): 8 distinct float4 in an 8-aligned block -> 1 wavefront.
// Writes (warp: rows 8g+k): 32 distinct banks -> 1 wavefront.
__device__ __forceinline__ int hword(int col, int b) {
    int c = (col >> 2) & 7, kk = col >> 5, j = col & 3;
    return b * HH + ((((c << 3) | (kk ^ c)) << 2) | j);
}

// fast tanh: 1 - 2/(e^{2x}+1), with exp folded into one ex2.approx and the
// final combine into one fmaf. Serial chain: FMUL+MUFU+FADD+MUFU+FFMA ~44cyc.
// Inf-safe: x>>0 -> e=inf -> r=0 -> 1 ; x<<0 -> e=0 -> r=1 -> -1.
__device__ __forceinline__ float ftanh(float x) {
    float e, r;
    asm("ex2.approx.f32 %0, %1;" : "=f"(e) : "f"(x * 2.8853900817779268f)); // 2*log2(e)
    asm("rcp.approx.f32 %0, %1;" : "=f"(r) : "f"(e + 1.0f));
    return fmaf(-2.0f, r, 1.0f);
}

__global__ void __launch_bounds__(NTHR, 1)
rnn_persistent_kernel(const float* __restrict__ x,
                      const float* __restrict__ W_ih,
                      const float* __restrict__ W_hh,
                      const float* __restrict__ b_ih,
                      const float* __restrict__ b_hh,
                      const float* __restrict__ W_out,
                      const float* __restrict__ b_out,
                      float* __restrict__ out)
{
    extern __shared__ char smem[];
    ulonglong2* sW   = (ulonglong2*)smem;
    float*      hbuf = (float*)(smem + SW_BYTES);
    u64*        sx2  = (u64*)(smem + SW_BYTES + HB_BYTES);

    const int t  = threadIdx.x;
    const int g  = t >> 3;      // row group: rows 8g..8g+7
    const int k  = t & 7;       // column strip: cols 32k..32k+31
    const int b0 = blockIdx.x * BC;

    // ---- Prologue.
    // Slot-swizzle: physical slot jp holds logical row (jp ^ k) -> select-free tree;
    // lane k still ends owning row 8g+k.
    // Slots 0..4 -> registers (40 float4 = 160 regs). Slots 5,6,7 -> smem.
    const ulonglong2* Wv = (const ulonglong2*)W_hh;   // row stride = 64 float4
    ulonglong2 wr[40];
#pragma unroll
    for (int jp = 0; jp < 5; jp++)
#pragma unroll
        for (int c = 0; c < 8; c++)
            wr[jp*8 + c] = Wv[(size_t)(8*g + (jp ^ k)) * 64 + k*8 + c];
#pragma unroll
    for (int jp = 0; jp < 3; jp++)
#pragma unroll
        for (int c = 0; c < 8; c++)
            sW[(jp*8 + c) * NTHR + t] = Wv[(size_t)(8*g + ((5 + jp) ^ k)) * 64 + k*8 + c];

    // lane-owned outputs after reduction: row 8g+k, both batches
    const int myrow  = 8*g + k;
    const float bias = b_ih[myrow] + b_hh[myrow];
    const float wih  = W_ih[myrow];
    const int wpos0  = hword(myrow, 0);
    const int wpos1  = hword(myrow, 1);

    // stage x as interleaved (b0, b1) pairs
    {
        const float* xg0 = x + (size_t)b0 * TT;
        const float* xg1 = x + (size_t)(b0 + 1) * TT;
#pragma unroll
        for (int q = t; q < TT; q += NTHR) {
            float2 p; p.x = xg0[q]; p.y = xg1[q];
            u64 v; asm("mov.b64 %0, {%1, %2};" : "=l"(v) : "f"(p.x), "f"(p.y));
            sx2[q] = v;
        }
    }
    hbuf[t] = 0.0f; hbuf[NTHR + t] = 0.0f;   // zero h buffer 0
    __syncthreads();

    int rb = 0;
    for (int ts = 0; ts < TT; ts++) {
        const ulonglong2* hr = (const ulonglong2*)(hbuf + rb * (BC * HH));

        // hoisted input projection (h-independent): one LDS.64 + unpack
        float2 xf = unpk(sx2[ts]);
        const float pre0b = fmaf(xf.x, wih, bias);
        const float pre1b = fmaf(xf.y, wih, bias);

        u64 A[16];   // A[jp*2 + b] : partial for logical row (jp^k)
#pragma unroll
        for (int c = 0; c < 8; c++) {
            const int m0 = k ^ c;
            ulonglong2 h0 = hr[c*8 + m0];
            ulonglong2 h1 = hr[64 + c*8 + m0];
            ulonglong2 w5 = sW[c * NTHR + t];
            ulonglong2 w6 = sW[(8 + c) * NTHR + t];
            ulonglong2 w7 = sW[(16 + c) * NTHR + t];
            if (c == 0) {
#pragma unroll
                for (int jp = 0; jp < 5; jp++) {
                    ulonglong2 w = wr[jp*8];
                    mul2(A[jp*2],   h0.x, w.x); fma2(A[jp*2],   h0.y, w.y);
                    mul2(A[jp*2+1], h1.x, w.x); fma2(A[jp*2+1], h1.y, w.y);
                }
                mul2(A[10], h0.x, w5.x); fma2(A[10], h0.y, w5.y);
                mul2(A[11], h1.x, w5.x); fma2(A[11], h1.y, w5.y);
                mul2(A[12], h0.x, w6.x); fma2(A[12], h0.y, w6.y);
                mul2(A[13], h1.x, w6.x); fma2(A[13], h1.y, w6.y);
                mul2(A[14], h0.x, w7.x); fma2(A[14], h0.y, w7.y);
                mul2(A[15], h1.x, w7.x); fma2(A[15], h1.y, w7.y);
            } else {
#pragma unroll
                for (int jp = 0; jp < 5; jp++) {
                    ulonglong2 w = wr[jp*8 + c];
                    fma2(A[jp*2],   h0.x, w.x); fma2(A[jp*2],   h0.y, w.y);
                    fma2(A[jp*2+1], h1.x, w.x); fma2(A[jp*2+1], h1.y, w.y);
                }
                fma2(A[10], h0.x, w5.x); fma2(A[10], h0.y, w5.y);
                fma2(A[11], h1.x, w5.x); fma2(A[11], h1.y, w5.y);
                fma2(A[12], h0.x, w6.x); fma2(A[12], h0.y, w6.y);
                fma2(A[13], h1.x, w6.x); fma2(A[13], h1.y, w6.y);
                fma2(A[14], h0.x, w7.x); fma2(A[14], h0.y, w7.y);
                fma2(A[15], h1.x, w7.x); fma2(A[15], h1.y, w7.y);
            }
        }

        float s[16];
#pragma unroll
        for (int m = 0; m < 16; m++) { float2 f = unpk(A[m]); s[m] = f.x + f.y; }

        // Select-free tree (slot-swizzled accumulators).
        float r8[8];
#pragma unroll
        for (int q = 0; q < 8; q++)
            r8[q] = s[q] + __shfl_xor_sync(0xffffffffu, s[q + 8], 4);
        float r4[4];
#pragma unroll
        for (int q = 0; q < 4; q++)
            r4[q] = r8[q] + __shfl_xor_sync(0xffffffffu, r8[q + 4], 2);
        float v0 = r4[0] + __shfl_xor_sync(0xffffffffu, r4[2], 1);
        float v1 = r4[1] + __shfl_xor_sync(0xffffffffu, r4[3], 1);

        const int wo = (rb ^ 1) * (BC * HH);
        hbuf[wo + wpos0] = ftanh(v0 + pre0b);
        hbuf[wo + wpos1] = ftanh(v1 + pre1b);
        __syncthreads();
        rb ^= 1;
    }

    // ---- Epilogue: out[b,p] = h_T[b,:] . W_out[p,:] + b_out[p]  (h in buf 0)
    if (t < BC * PP) {
        const int bb = t / PP;
        const int p  = t % PP;
        const float* wo = W_out + (size_t)p * HH;
        float acc = b_out[p];
#pragma unroll 8
        for (int col = 0; col < HH; col++)
            acc = fmaf(hbuf[hword(col, bb)], wo[col], acc);
        out[(size_t)(b0 + bb) * PP + p] = acc;
    }
}

extern "C" void kernel_launch(void* const* d_in, const int* in_sizes, int n_in,
                              void* d_out, int out_size)
{
    const float* x     = (const float*)d_in[0];
    const float* W_ih  = (const float*)d_in[1];
    const float* W_hh  = (const float*)d_in[2];
    const float* b_ih  = (const float*)d_in[3];
    const float* b_hh  = (const float*)d_in[4];
    const float* W_out = (const float*)d_in[5];
    const float* b_out = (const float*)d_in[6];
    float* out = (float*)d_out;

    cudaFuncSetAttribute(rnn_persistent_kernel,
                         cudaFuncAttributeMaxDynamicSharedMemorySize, (int)SMEM_TOTAL);
    rnn_persistent_kernel<<<NCTA, NTHR, SMEM_TOTAL>>>(x, W_ih, W_hh, b_ih, b_hh,
                                                      W_out, b_out, out);
}